// round 1
// baseline (speedup 1.0000x reference)
#include <cuda_runtime.h>
#include <cstdint>

// Problem constants: [B=8, C=3, N=1024, D=1024]
#define BCD   24      // B*C independent point-set pairs
#define NPTS  1024    // points per set
#define KDIM  1024    // dimensionality

// GEMM tiling
#define BM 128
#define BN 128
#define BK 16

// ---------------- scratch (static __device__, no allocation) ----------------
__device__ float g_x2[BCD * NPTS];     // ||x_n||^2 per (bc, n)
__device__ float g_y2[BCD * NPTS];     // ||y_m||^2 per (bc, m)
__device__ int   g_rowmin[BCD * NPTS]; // min_m d2  (float bits, all >= 0)
__device__ int   g_colmin[BCD * NPTS]; // min_n d2

// ---------------- init: set mins to +inf ----------------
__global__ void hd_init_kernel() {
    int i = blockIdx.x * blockDim.x + threadIdx.x;
    if (i < BCD * NPTS) {
        g_rowmin[i] = 0x7F800000; // +inf
        g_colmin[i] = 0x7F800000;
    }
}

// ---------------- norms: one warp per row, float4 strided loads ----------------
__global__ void hd_norms_kernel(const float* __restrict__ x,
                                const float* __restrict__ y) {
    int warp = (blockIdx.x * blockDim.x + threadIdx.x) >> 5;
    int lane = threadIdx.x & 31;
    const int total_rows = BCD * NPTS;          // per tensor
    if (warp >= 2 * total_rows) return;

    bool is_x = (warp < total_rows);
    int row = is_x ? warp : (warp - total_rows);
    const float4* p = (const float4*)((is_x ? x : y) + (size_t)row * KDIM);

    float s = 0.0f;
    #pragma unroll
    for (int j = 0; j < KDIM / 4 / 32; j++) {   // 8 iterations
        float4 v = p[lane + 32 * j];
        s += v.x * v.x + v.y * v.y + v.z * v.z + v.w * v.w;
    }
    #pragma unroll
    for (int off = 16; off > 0; off >>= 1)
        s += __shfl_down_sync(0xFFFFFFFFu, s, off);
    if (lane == 0) (is_x ? g_x2 : g_y2)[row] = s;
}

// ---------------- main fused GEMM + d2 + row/col-min ----------------
// C[n][m] = dot(X_n, Y_m); d2 = x2[n] + y2[m] - 2*C; track min over m (row)
// and min over n (col) via shared atomicMin then one global atomicMin each.
__global__ void __launch_bounds__(256, 2)
hd_gemm_kernel(const float* __restrict__ X, const float* __restrict__ Y) {
    int bc   = blockIdx.z;
    int nblk = blockIdx.y * BM;   // x-point rows
    int mblk = blockIdx.x * BN;   // y-point cols

    const float* A = X + (size_t)bc * NPTS * KDIM + (size_t)nblk * KDIM;
    const float* B = Y + (size_t)bc * NPTS * KDIM + (size_t)mblk * KDIM;

    __shared__ float As[BK][BM + 4];  // +4 keeps rows 16B-aligned, softens conflicts
    __shared__ float Bs[BK][BN + 4];
    __shared__ float sx2[BM];
    __shared__ float sy2[BN];
    __shared__ int   sminr[BM];
    __shared__ int   sminc[BN];

    int tid  = threadIdx.x;
    int trow = (tid >> 4) << 3;   // (tid/16)*8  -> 0..120
    int tcol = (tid & 15) << 3;   // (tid%16)*8  -> 0..120

    if (tid < BM) {
        sx2[tid]   = g_x2[bc * NPTS + nblk + tid];
        sy2[tid]   = g_y2[bc * NPTS + mblk + tid];
        sminr[tid] = 0x7F800000;
        sminc[tid] = 0x7F800000;
    }

    float acc[8][8];
    #pragma unroll
    for (int i = 0; i < 8; i++)
        #pragma unroll
        for (int j = 0; j < 8; j++)
            acc[i][j] = 0.0f;

    for (int k0 = 0; k0 < KDIM; k0 += BK) {
        // Load 128x16 tiles of A and B (512 float4 each; 2 per thread).
        #pragma unroll
        for (int i = 0; i < 2; i++) {
            int idx = tid + i * 256;       // 0..511
            int row = idx >> 2;            // 0..127
            int kq  = (idx & 3) << 2;      // 0,4,8,12
            float4 va = *(const float4*)(A + (size_t)row * KDIM + k0 + kq);
            As[kq + 0][row] = va.x; As[kq + 1][row] = va.y;
            As[kq + 2][row] = va.z; As[kq + 3][row] = va.w;
            float4 vb = *(const float4*)(B + (size_t)row * KDIM + k0 + kq);
            Bs[kq + 0][row] = vb.x; Bs[kq + 1][row] = vb.y;
            Bs[kq + 2][row] = vb.z; Bs[kq + 3][row] = vb.w;
        }
        __syncthreads();

        #pragma unroll
        for (int kk = 0; kk < BK; kk++) {
            float a[8], b[8];
            *(float4*)(a)     = *(const float4*)&As[kk][trow];
            *(float4*)(a + 4) = *(const float4*)&As[kk][trow + 4];
            *(float4*)(b)     = *(const float4*)&Bs[kk][tcol];
            *(float4*)(b + 4) = *(const float4*)&Bs[kk][tcol + 4];
            #pragma unroll
            for (int i = 0; i < 8; i++)
                #pragma unroll
                for (int j = 0; j < 8; j++)
                    acc[i][j] = fmaf(a[i], b[j], acc[i][j]);
        }
        __syncthreads();
    }

    // Epilogue: d2 + local row/col mins
    float rmin[8], cmin[8];
    #pragma unroll
    for (int i = 0; i < 8; i++) { rmin[i] = 3.4e38f; cmin[i] = 3.4e38f; }

    #pragma unroll
    for (int i = 0; i < 8; i++) {
        float xi = sx2[trow + i];
        #pragma unroll
        for (int j = 0; j < 8; j++) {
            float d2 = fmaxf(xi + sy2[tcol + j] - 2.0f * acc[i][j], 0.0f);
            rmin[i] = fminf(rmin[i], d2);
            cmin[j] = fminf(cmin[j], d2);
        }
    }

    #pragma unroll
    for (int i = 0; i < 8; i++)
        atomicMin(&sminr[trow + i], __float_as_int(rmin[i]));
    #pragma unroll
    for (int j = 0; j < 8; j++)
        atomicMin(&sminc[tcol + j], __float_as_int(cmin[j]));
    __syncthreads();

    if (tid < BM) {
        atomicMin(&g_rowmin[bc * NPTS + nblk + tid], sminr[tid]);
        atomicMin(&g_colmin[bc * NPTS + mblk + tid], sminc[tid]);
    }
}

// ---------------- final reduction: max over mins, sqrt, mean ----------------
__global__ void hd_reduce_kernel(float* __restrict__ out) {
    __shared__ float red[256];
    int tid = threadIdx.x;
    float total = 0.0f;

    for (int bc = 0; bc < BCD; bc++) {
        float m = 0.0f;   // d2 >= 0
        for (int i = tid; i < 2 * NPTS; i += 256) {
            float v = (i < NPTS) ? __int_as_float(g_rowmin[bc * NPTS + i])
                                 : __int_as_float(g_colmin[bc * NPTS + i - NPTS]);
            m = fmaxf(m, v);
        }
        red[tid] = m;
        __syncthreads();
        for (int s = 128; s > 0; s >>= 1) {
            if (tid < s) red[tid] = fmaxf(red[tid], red[tid + s]);
            __syncthreads();
        }
        total += sqrtf(red[0]);
        __syncthreads();
    }
    if (tid == 0) out[0] = total / (float)BCD;
}

// ---------------- launch ----------------
extern "C" void kernel_launch(void* const* d_in, const int* in_sizes, int n_in,
                              void* d_out, int out_size) {
    const float* x = (const float*)d_in[0];  // input
    const float* y = (const float*)d_in[1];  // target
    float* out = (float*)d_out;

    hd_init_kernel<<<(BCD * NPTS + 255) / 256, 256>>>();
    hd_norms_kernel<<<(2 * BCD * NPTS) / 8, 256>>>(x, y);  // 1 warp/row, 8 warps/block

    dim3 grid(NPTS / BN, NPTS / BM, BCD);  // (8, 8, 24)
    hd_gemm_kernel<<<grid, 256>>>(x, y);

    hd_reduce_kernel<<<1, 256>>>(out);
}

// round 4
// speedup vs baseline: 6.1577x; 6.1577x over previous
#include <cuda_runtime.h>
#include <cuda_fp16.h>
#include <cstdint>

// Problem: [B=8, C=3, N=1024, D=1024]
#define BCD    24
#define NPTS   1024
#define KDIM   1024

#define BM     128
#define BN     128
#define BKH    32              // k halves per stage (64 bytes/row)
#define NSTAGE 4
#define NKITER (KDIM / BKH)    // 32
#define ROWB   64              // smem bytes per row
#define A_BYTES (BM * ROWB)    // 8192
#define STAGE_BYTES (2 * A_BYTES)
#define DSMEM_BYTES (NSTAGE * STAGE_BYTES)   // 65536

// ---------------- scratch ----------------
__device__ __half g_xh[(size_t)BCD * NPTS * KDIM];   // fp16 copies (48MB each)
__device__ __half g_yh[(size_t)BCD * NPTS * KDIM];
__device__ float g_x2[BCD * NPTS];
__device__ float g_y2[BCD * NPTS];
__device__ int   g_rowmin[BCD * NPTS];
__device__ int   g_colmin[BCD * NPTS];

// ---------------- helpers ----------------
__device__ __forceinline__ uint32_t smem_u32(const void* p) {
    uint32_t a;
    asm("{ .reg .u64 t; cvta.to.shared.u64 t, %1; cvt.u32.u64 %0, t; }" : "=r"(a) : "l"(p));
    return a;
}
__device__ __forceinline__ void cp16(uint32_t dst, const void* src) {
    asm volatile("cp.async.cg.shared.global [%0], [%1], 16;" :: "r"(dst), "l"(src));
}
__device__ __forceinline__ void cp_commit() {
    asm volatile("cp.async.commit_group;" ::: "memory");
}
// XOR swizzle: row stride 64B, permute the four 16B chunks by (row>>1)&3.
// Guarantees 8 ldmatrix addresses land on 8 distinct 16B bank groups mod 128B.
__device__ __forceinline__ uint32_t swz(int row, int c) {
    return (uint32_t)(row * ROWB + ((c ^ ((row >> 1) & 3)) << 4));
}
#define LDSM4(r0, r1, r2, r3, addr)                                          \
    asm volatile("ldmatrix.sync.aligned.m8n8.x4.shared.b16 {%0,%1,%2,%3}, [%4];" \
                 : "=r"(r0), "=r"(r1), "=r"(r2), "=r"(r3) : "r"(addr))
#define MMA16816(c, a, b)                                                    \
    asm volatile("mma.sync.aligned.m16n8k16.row.col.f32.f16.f16.f32 "        \
                 "{%0,%1,%2,%3}, {%4,%5,%6,%7}, {%8,%9}, {%0,%1,%2,%3};"     \
                 : "+f"((c)[0]), "+f"((c)[1]), "+f"((c)[2]), "+f"((c)[3])    \
                 : "r"((a)[0]), "r"((a)[1]), "r"((a)[2]), "r"((a)[3]),       \
                   "r"((b)[0]), "r"((b)[1]))

// ---------------- init ----------------
__global__ void hd_init_kernel(float* out) {
    int i = blockIdx.x * blockDim.x + threadIdx.x;
    if (i < BCD * NPTS) {
        g_rowmin[i] = 0x7F800000;
        g_colmin[i] = 0x7F800000;
    }
    if (i == 0) out[0] = 0.0f;
}

// ---------------- fp32 -> fp16 conversion (8 elems / thread) ----------------
__global__ void hd_convert(const float* __restrict__ x, const float* __restrict__ y) {
    size_t i = ((size_t)blockIdx.x * blockDim.x + threadIdx.x) * 8;
    const float* src = blockIdx.y ? y : x;
    __half* dst = blockIdx.y ? g_yh : g_xh;
    float4 v0 = *(const float4*)(src + i);
    float4 v1 = *(const float4*)(src + i + 4);
    __half2 h0 = __floats2half2_rn(v0.x, v0.y);
    __half2 h1 = __floats2half2_rn(v0.z, v0.w);
    __half2 h2 = __floats2half2_rn(v1.x, v1.y);
    __half2 h3 = __floats2half2_rn(v1.z, v1.w);
    uint4 o;
    o.x = *(uint32_t*)&h0; o.y = *(uint32_t*)&h1;
    o.z = *(uint32_t*)&h2; o.w = *(uint32_t*)&h3;
    *(uint4*)(dst + i) = o;
}

// ---------------- norms from fp16 values (consistency with MMA) ----------------
__global__ void hd_norms_kernel() {
    int warp = (blockIdx.x * blockDim.x + threadIdx.x) >> 5;
    int lane = threadIdx.x & 31;
    const int total = BCD * NPTS;
    if (warp >= 2 * total) return;
    bool is_x = (warp < total);
    int row = is_x ? warp : (warp - total);
    const uint4* p = (const uint4*)((is_x ? g_xh : g_yh) + (size_t)row * KDIM);
    float s = 0.0f;
    #pragma unroll
    for (int j = 0; j < KDIM / 8 / 32; j++) {   // 4 iters, 8 halves each
        uint4 u = p[lane + 32 * j];
        __half2* h = (__half2*)&u;
        #pragma unroll
        for (int t = 0; t < 4; t++) {
            float2 f = __half22float2(h[t]);
            s += f.x * f.x + f.y * f.y;
        }
    }
    #pragma unroll
    for (int off = 16; off > 0; off >>= 1)
        s += __shfl_down_sync(0xFFFFFFFFu, s, off);
    if (lane == 0) (is_x ? g_x2 : g_y2)[row] = s;
}

// ---------------- stage loader ----------------
__device__ __forceinline__ void load_stage(int it, int tid, uint32_t sbase,
                                           const __half* __restrict__ gA,
                                           const __half* __restrict__ gB) {
    if (it < NKITER) {
        uint32_t sb = sbase + (it & (NSTAGE - 1)) * STAGE_BYTES;
        int k0 = it * BKH;
        #pragma unroll
        for (int t = 0; t < 2; t++) {
            int idx = tid + t * 256;          // 0..511
            int row = idx >> 2;               // 0..127
            int c = idx & 3;                  // 16B chunk
            cp16(sb + swz(row, c),           gA + (size_t)row * KDIM + k0 + c * 8);
            cp16(sb + A_BYTES + swz(row, c), gB + (size_t)row * KDIM + k0 + c * 8);
        }
    }
    cp_commit();
}

// ---------------- main MMA GEMM + fused min epilogue ----------------
__global__ void __launch_bounds__(256, 2)
hd_gemm_mma() {
    extern __shared__ char smem[];
    __shared__ float sx2[BM], sy2[BN];
    __shared__ int sminr[BM], sminc[BN];

    int tid = threadIdx.x, lane = tid & 31, wid = tid >> 5;
    int warp_m = wid & 3, warp_n = wid >> 2;     // 4x2 warps, warp tile 32x64
    int bc = blockIdx.z, nblk = blockIdx.y * BM, mblk = blockIdx.x * BN;
    const __half* gA = g_xh + ((size_t)bc * NPTS + nblk) * KDIM;
    const __half* gB = g_yh + ((size_t)bc * NPTS + mblk) * KDIM;
    uint32_t sbase = smem_u32(smem);

    if (tid < BM) {
        sx2[tid] = g_x2[bc * NPTS + nblk + tid];
        sy2[tid] = g_y2[bc * NPTS + mblk + tid];
        sminr[tid] = 0x7F800000;
        sminc[tid] = 0x7F800000;
    }

    float acc[2][8][4];
    #pragma unroll
    for (int mt = 0; mt < 2; mt++)
        #pragma unroll
        for (int nt = 0; nt < 8; nt++)
            #pragma unroll
            for (int e = 0; e < 4; e++) acc[mt][nt][e] = 0.0f;

    load_stage(0, tid, sbase, gA, gB);
    load_stage(1, tid, sbase, gA, gB);
    load_stage(2, tid, sbase, gA, gB);

    // ldmatrix per-thread address components
    int lr = lane & 7, grp = lane >> 3;
    int arow0 = warp_m * 32 + lr + ((grp & 1) << 3);   // + mt*16
    int brow0 = warp_n * 64 + lr + ((grp >> 1) << 3);  // + bt*16
    int ac_x = grp >> 1;   // chunk offset for A
    int bc_x = grp & 1;    // chunk offset for B

    for (int i = 0; i < NKITER; i++) {
        asm volatile("cp.async.wait_group 2;" ::: "memory");
        __syncthreads();
        uint32_t sA = sbase + (i & (NSTAGE - 1)) * STAGE_BYTES;
        uint32_t sB = sA + A_BYTES;
        #pragma unroll
        for (int ks = 0; ks < 2; ks++) {       // two k16 steps per stage
            uint32_t a[2][4], b[8][2];
            #pragma unroll
            for (int mt = 0; mt < 2; mt++) {
                int row = arow0 + mt * 16;
                uint32_t addr = sA + swz(row, ks * 2 + ac_x);
                LDSM4(a[mt][0], a[mt][1], a[mt][2], a[mt][3], addr);
            }
            #pragma unroll
            for (int bt = 0; bt < 4; bt++) {
                int row = brow0 + bt * 16;
                uint32_t addr = sB + swz(row, ks * 2 + bc_x);
                uint32_t r0, r1, r2, r3;
                LDSM4(r0, r1, r2, r3, addr);
                b[bt * 2][0] = r0;     b[bt * 2][1] = r1;
                b[bt * 2 + 1][0] = r2; b[bt * 2 + 1][1] = r3;
            }
            #pragma unroll
            for (int mt = 0; mt < 2; mt++)
                #pragma unroll
                for (int nt = 0; nt < 8; nt++)
                    MMA16816(acc[mt][nt], a[mt], b[nt]);
        }
        load_stage(i + 3, tid, sbase, gA, gB);
    }

    // ---- fused epilogue: d2 + row/col mins ----
    int g = lane >> 2, l = lane & 3;
    float xr[4], yc[16];
    #pragma unroll
    for (int r = 0; r < 4; r++)
        xr[r] = sx2[warp_m * 32 + (r >> 1) * 16 + ((r & 1) << 3) + g];
    #pragma unroll
    for (int c = 0; c < 16; c++)
        yc[c] = sy2[warp_n * 64 + (c >> 1) * 8 + l * 2 + (c & 1)];

    float rmin[4], cmin[16];
    #pragma unroll
    for (int r = 0; r < 4; r++) rmin[r] = 3.4e38f;
    #pragma unroll
    for (int c = 0; c < 16; c++) cmin[c] = 3.4e38f;

    #pragma unroll
    for (int mt = 0; mt < 2; mt++)
        #pragma unroll
        for (int nt = 0; nt < 8; nt++)
            #pragma unroll
            for (int e = 0; e < 4; e++) {
                int rid = mt * 2 + (e >> 1);
                int cid = nt * 2 + (e & 1);
                float d2 = fmaxf(xr[rid] + yc[cid] - 2.0f * acc[mt][nt][e], 0.0f);
                rmin[rid] = fminf(rmin[rid], d2);
                cmin[cid] = fminf(cmin[cid], d2);
            }

    #pragma unroll
    for (int r = 0; r < 4; r++) {
        rmin[r] = fminf(rmin[r], __shfl_xor_sync(0xFFFFFFFFu, rmin[r], 1));
        rmin[r] = fminf(rmin[r], __shfl_xor_sync(0xFFFFFFFFu, rmin[r], 2));
    }
    #pragma unroll
    for (int c = 0; c < 16; c++) {
        cmin[c] = fminf(cmin[c], __shfl_xor_sync(0xFFFFFFFFu, cmin[c], 4));
        cmin[c] = fminf(cmin[c], __shfl_xor_sync(0xFFFFFFFFu, cmin[c], 8));
        cmin[c] = fminf(cmin[c], __shfl_xor_sync(0xFFFFFFFFu, cmin[c], 16));
    }
    if (l == 0) {
        #pragma unroll
        for (int r = 0; r < 4; r++)
            atomicMin(&sminr[warp_m * 32 + (r >> 1) * 16 + ((r & 1) << 3) + g],
                      __float_as_int(rmin[r]));
    }
    if (g == 0) {
        #pragma unroll
        for (int c = 0; c < 16; c++)
            atomicMin(&sminc[warp_n * 64 + (c >> 1) * 8 + l * 2 + (c & 1)],
                      __float_as_int(cmin[c]));
    }
    __syncthreads();
    if (tid < BM) {
        atomicMin(&g_rowmin[bc * NPTS + nblk + tid], sminr[tid]);
        atomicMin(&g_colmin[bc * NPTS + mblk + tid], sminc[tid]);
    }
}

// ---------------- final reduction: one block per (b,c) ----------------
__global__ void hd_reduce_kernel(float* __restrict__ out) {
    __shared__ float red[256];
    int bc = blockIdx.x, tid = threadIdx.x;
    float m = 0.0f;
    for (int i = tid; i < 2 * NPTS; i += 256) {
        float v = (i < NPTS) ? __int_as_float(g_rowmin[bc * NPTS + i])
                             : __int_as_float(g_colmin[bc * NPTS + i - NPTS]);
        m = fmaxf(m, v);
    }
    red[tid] = m;
    __syncthreads();
    for (int s = 128; s > 0; s >>= 1) {
        if (tid < s) red[tid] = fmaxf(red[tid], red[tid + s]);
        __syncthreads();
    }
    if (tid == 0) atomicAdd(out, sqrtf(red[0]) * (1.0f / BCD));
}

// ---------------- launch ----------------
extern "C" void kernel_launch(void* const* d_in, const int* in_sizes, int n_in,
                              void* d_out, int out_size) {
    const float* x = (const float*)d_in[0];
    const float* y = (const float*)d_in[1];
    float* out = (float*)d_out;

    cudaFuncSetAttribute(hd_gemm_mma, cudaFuncAttributeMaxDynamicSharedMemorySize, DSMEM_BYTES);

    hd_init_kernel<<<(BCD * NPTS + 255) / 256, 256>>>(out);

    int conv_threads = BCD * NPTS * KDIM / 8;           // 3145728 per tensor
    hd_convert<<<dim3(conv_threads / 256, 2), 256>>>(x, y);

    hd_norms_kernel<<<(2 * BCD * NPTS * 32) / 256, 256>>>();

    dim3 grid(NPTS / BN, NPTS / BM, BCD);               // (8, 8, 24)
    hd_gemm_mma<<<grid, 256, DSMEM_BYTES>>>();

    hd_reduce_kernel<<<BCD, 256>>>(out);
}

// round 6
// speedup vs baseline: 6.8884x; 1.1187x over previous
#include <cuda_runtime.h>
#include <cuda_fp16.h>
#include <cstdint>

// Problem: [B=8, C=3, N=1024, D=1024]
#define BCD    24
#define NPTS   1024
#define KDIM   1024

#define BM     128
#define BN     128
#define BKH    64              // k halves per stage (128 bytes/row)
#define NSTAGE 3
#define NKITER (KDIM / BKH)    // 16
#define ROWB   128             // smem bytes per row
#define A_BYTES (BM * ROWB)    // 16384
#define STAGE_BYTES (2 * A_BYTES)            // 32768
#define DSMEM_BYTES (NSTAGE * STAGE_BYTES)   // 98304

// ---------------- scratch ----------------
__device__ __half g_xh[(size_t)BCD * NPTS * KDIM];
__device__ __half g_yh[(size_t)BCD * NPTS * KDIM];
__device__ float g_x2[BCD * NPTS];
__device__ float g_y2[BCD * NPTS];
__device__ int   g_rowmin[BCD * NPTS];
__device__ int   g_colmin[BCD * NPTS];

// ---------------- helpers ----------------
__device__ __forceinline__ uint32_t smem_u32(const void* p) {
    uint32_t a;
    asm("{ .reg .u64 t; cvta.to.shared.u64 t, %1; cvt.u32.u64 %0, t; }" : "=r"(a) : "l"(p));
    return a;
}
__device__ __forceinline__ void cp16(uint32_t dst, const void* src) {
    asm volatile("cp.async.cg.shared.global [%0], [%1], 16;" :: "r"(dst), "l"(src));
}
__device__ __forceinline__ void cp_commit() {
    asm volatile("cp.async.commit_group;" ::: "memory");
}
// 128B-row XOR swizzle: chunk c (16B) of row r -> c ^ (r & 7).
__device__ __forceinline__ uint32_t swz(int row, int c) {
    return (uint32_t)(row * ROWB + ((c ^ (row & 7)) << 4));
}
#define LDSM4(r0, r1, r2, r3, addr)                                          \
    asm volatile("ldmatrix.sync.aligned.m8n8.x4.shared.b16 {%0,%1,%2,%3}, [%4];" \
                 : "=r"(r0), "=r"(r1), "=r"(r2), "=r"(r3) : "r"(addr))
#define MMA16816(c, a, b)                                                    \
    asm volatile("mma.sync.aligned.m16n8k16.row.col.f32.f16.f16.f32 "        \
                 "{%0,%1,%2,%3}, {%4,%5,%6,%7}, {%8,%9}, {%0,%1,%2,%3};"     \
                 : "+f"((c)[0]), "+f"((c)[1]), "+f"((c)[2]), "+f"((c)[3])    \
                 : "r"((a)[0]), "r"((a)[1]), "r"((a)[2]), "r"((a)[3]),       \
                   "r"((b)[0]), "r"((b)[1]))

// ---------------- init ----------------
__global__ void hd_init_kernel(float* out) {
    int i = blockIdx.x * blockDim.x + threadIdx.x;
    if (i < BCD * NPTS) {
        g_rowmin[i] = 0x7F800000;
        g_colmin[i] = 0x7F800000;
    }
    if (i == 0) out[0] = 0.0f;
}

// ---------------- fused fp32->fp16 convert + row norms ----------------
// Block = 256 threads = 2 rows (128 threads/row, 8 elems/thread).
__global__ void hd_convert_norms(const float* __restrict__ x, const float* __restrict__ y) {
    __shared__ float part[8];
    int tid = threadIdx.x;
    size_t base = ((size_t)blockIdx.x * 256 + tid) * 8;
    const float* src = blockIdx.y ? y : x;
    __half* dst = blockIdx.y ? g_yh : g_xh;
    float* nrm = blockIdx.y ? g_y2 : g_x2;

    float4 v0 = *(const float4*)(src + base);
    float4 v1 = *(const float4*)(src + base + 4);
    __half2 h0 = __floats2half2_rn(v0.x, v0.y);
    __half2 h1 = __floats2half2_rn(v0.z, v0.w);
    __half2 h2 = __floats2half2_rn(v1.x, v1.y);
    __half2 h3 = __floats2half2_rn(v1.z, v1.w);
    uint4 o;
    o.x = *(uint32_t*)&h0; o.y = *(uint32_t*)&h1;
    o.z = *(uint32_t*)&h2; o.w = *(uint32_t*)&h3;
    *(uint4*)(dst + base) = o;

    // norm of the *converted* values (consistency with the MMA products)
    float s = 0.0f;
    {
        float2 f;
        f = __half22float2(h0); s += f.x * f.x + f.y * f.y;
        f = __half22float2(h1); s += f.x * f.x + f.y * f.y;
        f = __half22float2(h2); s += f.x * f.x + f.y * f.y;
        f = __half22float2(h3); s += f.x * f.x + f.y * f.y;
    }
    #pragma unroll
    for (int off = 16; off > 0; off >>= 1)
        s += __shfl_down_sync(0xFFFFFFFFu, s, off);
    if ((tid & 31) == 0) part[tid >> 5] = s;
    __syncthreads();
    if (tid < 2) {
        float t = part[tid * 4] + part[tid * 4 + 1] + part[tid * 4 + 2] + part[tid * 4 + 3];
        nrm[blockIdx.x * 2 + tid] = t;
    }
}

// ---------------- stage loader ----------------
__device__ __forceinline__ void load_stage(int it, int tid, uint32_t sbase,
                                           const __half* __restrict__ gA,
                                           const __half* __restrict__ gB) {
    if (it < NKITER) {
        uint32_t sb = sbase + (it % NSTAGE) * STAGE_BYTES;
        int k0 = it * BKH;
        #pragma unroll
        for (int t = 0; t < 4; t++) {
            int idx = tid + t * 256;          // 0..1023
            int row = idx >> 3;               // 0..127
            int c = idx & 7;                  // 16B chunk (8 per row)
            cp16(sb + swz(row, c),           gA + (size_t)row * KDIM + k0 + c * 8);
            cp16(sb + A_BYTES + swz(row, c), gB + (size_t)row * KDIM + k0 + c * 8);
        }
    }
    cp_commit();
}

// ---------------- main MMA GEMM + fused min epilogue ----------------
__global__ void __launch_bounds__(256, 2)
hd_gemm_mma() {
    extern __shared__ char smem[];
    __shared__ float sx2[BM], sy2[BN];
    __shared__ int sminr[BM], sminc[BN];

    int tid = threadIdx.x, lane = tid & 31, wid = tid >> 5;
    int warp_m = wid & 3, warp_n = wid >> 2;     // 4x2 warps, warp tile 32x64
    int bc = blockIdx.z, nblk = blockIdx.y * BM, mblk = blockIdx.x * BN;
    const __half* gA = g_xh + ((size_t)bc * NPTS + nblk) * KDIM;
    const __half* gB = g_yh + ((size_t)bc * NPTS + mblk) * KDIM;
    uint32_t sbase = smem_u32(smem);

    if (tid < BM) {
        sx2[tid] = g_x2[bc * NPTS + nblk + tid];
        sy2[tid] = g_y2[bc * NPTS + mblk + tid];
        sminr[tid] = 0x7F800000;
        sminc[tid] = 0x7F800000;
    }

    float acc[2][8][4];
    #pragma unroll
    for (int mt = 0; mt < 2; mt++)
        #pragma unroll
        for (int nt = 0; nt < 8; nt++)
            #pragma unroll
            for (int e = 0; e < 4; e++) acc[mt][nt][e] = 0.0f;

    load_stage(0, tid, sbase, gA, gB);
    load_stage(1, tid, sbase, gA, gB);

    // ldmatrix per-thread address components
    int lr = lane & 7, grp = lane >> 3;
    int arow0 = warp_m * 32 + lr + ((grp & 1) << 3);   // + mt*16
    int brow0 = warp_n * 64 + lr + ((grp >> 1) << 3);  // + bt*16
    int ac_x = grp >> 1;   // A chunk offset within k16 step
    int bc_x = grp & 1;    // B chunk offset

    for (int i = 0; i < NKITER; i++) {
        asm volatile("cp.async.wait_group 1;" ::: "memory");
        __syncthreads();
        load_stage(i + 2, tid, sbase, gA, gB);
        uint32_t sA = sbase + (i % NSTAGE) * STAGE_BYTES;
        uint32_t sB = sA + A_BYTES;
        #pragma unroll
        for (int ks = 0; ks < 4; ks++) {       // four k16 steps per stage
            uint32_t a[2][4], b[8][2];
            #pragma unroll
            for (int mt = 0; mt < 2; mt++) {
                int row = arow0 + mt * 16;
                uint32_t addr = sA + swz(row, ks * 2 + ac_x);
                LDSM4(a[mt][0], a[mt][1], a[mt][2], a[mt][3], addr);
            }
            #pragma unroll
            for (int bt = 0; bt < 4; bt++) {
                int row = brow0 + bt * 16;
                uint32_t addr = sB + swz(row, ks * 2 + bc_x);
                uint32_t r0, r1, r2, r3;
                LDSM4(r0, r1, r2, r3, addr);
                b[bt * 2][0] = r0;     b[bt * 2][1] = r1;
                b[bt * 2 + 1][0] = r2; b[bt * 2 + 1][1] = r3;
            }
            #pragma unroll
            for (int mt = 0; mt < 2; mt++)
                #pragma unroll
                for (int nt = 0; nt < 8; nt++)
                    MMA16816(acc[mt][nt], a[mt], b[nt]);
        }
    }

    // ---- fused epilogue: d2 + row/col mins ----
    int g = lane >> 2, l = lane & 3;
    float xr[4], yc[16];
    #pragma unroll
    for (int r = 0; r < 4; r++)
        xr[r] = sx2[warp_m * 32 + (r >> 1) * 16 + ((r & 1) << 3) + g];
    #pragma unroll
    for (int c = 0; c < 16; c++)
        yc[c] = sy2[warp_n * 64 + (c >> 1) * 8 + l * 2 + (c & 1)];

    float rmin[4], cmin[16];
    #pragma unroll
    for (int r = 0; r < 4; r++) rmin[r] = 3.4e38f;
    #pragma unroll
    for (int c = 0; c < 16; c++) cmin[c] = 3.4e38f;

    #pragma unroll
    for (int mt = 0; mt < 2; mt++)
        #pragma unroll
        for (int nt = 0; nt < 8; nt++)
            #pragma unroll
            for (int e = 0; e < 4; e++) {
                int rid = mt * 2 + (e >> 1);
                int cid = nt * 2 + (e & 1);
                float d2 = fmaxf(xr[rid] + yc[cid] - 2.0f * acc[mt][nt][e], 0.0f);
                rmin[rid] = fminf(rmin[rid], d2);
                cmin[cid] = fminf(cmin[cid], d2);
            }

    #pragma unroll
    for (int r = 0; r < 4; r++) {
        rmin[r] = fminf(rmin[r], __shfl_xor_sync(0xFFFFFFFFu, rmin[r], 1));
        rmin[r] = fminf(rmin[r], __shfl_xor_sync(0xFFFFFFFFu, rmin[r], 2));
    }
    #pragma unroll
    for (int c = 0; c < 16; c++) {
        cmin[c] = fminf(cmin[c], __shfl_xor_sync(0xFFFFFFFFu, cmin[c], 4));
        cmin[c] = fminf(cmin[c], __shfl_xor_sync(0xFFFFFFFFu, cmin[c], 8));
        cmin[c] = fminf(cmin[c], __shfl_xor_sync(0xFFFFFFFFu, cmin[c], 16));
    }
    if (l == 0) {
        #pragma unroll
        for (int r = 0; r < 4; r++)
            atomicMin(&sminr[warp_m * 32 + (r >> 1) * 16 + ((r & 1) << 3) + g],
                      __float_as_int(rmin[r]));
    }
    if (g == 0) {
        #pragma unroll
        for (int c = 0; c < 16; c++)
            atomicMin(&sminc[warp_n * 64 + (c >> 1) * 8 + l * 2 + (c & 1)],
                      __float_as_int(cmin[c]));
    }
    __syncthreads();
    if (tid < BM) {
        atomicMin(&g_rowmin[bc * NPTS + nblk + tid], sminr[tid]);
        atomicMin(&g_colmin[bc * NPTS + mblk + tid], sminc[tid]);
    }
}

// ---------------- final reduction: one block per (b,c) ----------------
__global__ void hd_reduce_kernel(float* __restrict__ out) {
    __shared__ float red[256];
    int bc = blockIdx.x, tid = threadIdx.x;
    float m = 0.0f;
    for (int i = tid; i < 2 * NPTS; i += 256) {
        float v = (i < NPTS) ? __int_as_float(g_rowmin[bc * NPTS + i])
                             : __int_as_float(g_colmin[bc * NPTS + i - NPTS]);
        m = fmaxf(m, v);
    }
    red[tid] = m;
    __syncthreads();
    for (int s = 128; s > 0; s >>= 1) {
        if (tid < s) red[tid] = fmaxf(red[tid], red[tid + s]);
        __syncthreads();
    }
    if (tid == 0) atomicAdd(out, sqrtf(red[0]) * (1.0f / BCD));
}

// ---------------- launch ----------------
extern "C" void kernel_launch(void* const* d_in, const int* in_sizes, int n_in,
                              void* d_out, int out_size) {
    const float* x = (const float*)d_in[0];
    const float* y = (const float*)d_in[1];
    float* out = (float*)d_out;

    cudaFuncSetAttribute(hd_gemm_mma, cudaFuncAttributeMaxDynamicSharedMemorySize, DSMEM_BYTES);

    hd_init_kernel<<<(BCD * NPTS + 255) / 256, 256>>>(out);

    // 2 rows per block, grid.y selects tensor
    hd_convert_norms<<<dim3(BCD * NPTS / 2, 2), 256>>>(x, y);

    dim3 grid(NPTS / BN, NPTS / BM, BCD);               // (8, 8, 24)
    hd_gemm_mma<<<grid, 256, DSMEM_BYTES>>>();

    hd_reduce_kernel<<<BCD, 256>>>(out);
}